// round 12
// baseline (speedup 1.0000x reference)
#include <cuda_runtime.h>
#include <cuda_fp16.h>
#include <mma.h>
#include <cstdint>

using namespace nvcuda;

#define N_NODES 50000
#define N_EDGES 800000
#define D_IN    128
#define D_HID   512
#define D_OUT   128
#define D_CAT   (D_IN + D_HID)
#define CAP     128                       // slots per node (max degree ~36 for this dist)

// ---------------- device scratch (no allocations allowed) ----------------
__device__ __align__(16) __half g_Zh[(size_t)N_NODES * D_HID];   // relu(x@W+b) fp16
__device__ __align__(16) __half g_cat[(size_t)N_NODES * D_CAT];  // [Xh | agg_h]
__device__ __align__(16) __half g_Wh[(size_t)D_IN * D_HID];      // fc_w fp16
__device__ __align__(16) __half g_W2h[(size_t)D_CAT * D_OUT];    // weights fp16
__device__ __align__(16) int    g_deg[N_NODES];
__device__ __align__(16) int    g_elist[(size_t)N_NODES * CAP];  // bucketed targets

// ---------------- zero degree counters ----------------
__global__ __launch_bounds__(256) void zero_kernel() {
    int i = blockIdx.x * blockDim.x + threadIdx.x;
    if (i < N_NODES) g_deg[i] = 0;
}

// ---------------- direct bucket scatter (adjacency is int32 — proven R2/R3) ----------------
__global__ void scatter_kernel(const int* __restrict__ adj) {
    int e = blockIdx.x * blockDim.x + threadIdx.x;
    if (e < N_EDGES) {
        int src = adj[e];
        int trg = adj[N_EDGES + e];
        if ((unsigned)src < (unsigned)N_NODES && (unsigned)trg < (unsigned)N_NODES) {
            int pos = atomicAdd(&g_deg[src], 1);
            if (pos < CAP)
                g_elist[(size_t)src * CAP + pos] = trg;
        }
    }
}

// ---------------- conversions to fp16 ----------------
#define CONV_X_VECS (N_NODES * D_IN / 8)             // 800000 uint4s
__global__ void conv_all_kernel(const float* __restrict__ X,
                                const float* __restrict__ fcw,
                                const float* __restrict__ w2) {
    int idx = blockIdx.x * blockDim.x + threadIdx.x;
    if (idx < CONV_X_VECS) {
        int i = idx * 8;
        int row = i >> 7;
        int col = i & 127;
        float4 a = *(const float4*)(X + i);
        float4 b = *(const float4*)(X + i + 4);
        union { __half h[8]; uint4 u; } pk;
        pk.h[0] = __float2half_rn(a.x); pk.h[1] = __float2half_rn(a.y);
        pk.h[2] = __float2half_rn(a.z); pk.h[3] = __float2half_rn(a.w);
        pk.h[4] = __float2half_rn(b.x); pk.h[5] = __float2half_rn(b.y);
        pk.h[6] = __float2half_rn(b.z); pk.h[7] = __float2half_rn(b.w);
        *(uint4*)(g_cat + (size_t)row * D_CAT + col) = pk.u;
    }
    if (idx < D_IN * D_HID) g_Wh[idx] = __float2half_rn(fcw[idx]);
    if (idx < D_CAT * D_OUT) g_W2h[idx] = __float2half_rn(w2[idx]);
}

// ---------------- Z = relu(Xh @ Wh + b), dual column tiles ----------------
__global__ __launch_bounds__(256) void gemm_relu_wmma(const float* __restrict__ bias) {
    __shared__ union SMem {
        struct { __half A[128 * 40]; __half B[2][32 * 72]; } t;
        float C[8 * 32 * 36];
    } sm;

    const int bm = blockIdx.y * 128;
    const int bn0 = blockIdx.x * 64;   // group 0: bn0, group 1: bn0+256
    const int tid = threadIdx.x;
    const int warp = tid >> 5;
    const int lane = tid & 31;
    const int wm = warp >> 1;
    const int wn = warp & 1;

    wmma::fragment<wmma::accumulator, 16, 16, 16, float> acc[2][2][2];
#pragma unroll
    for (int g = 0; g < 2; ++g)
#pragma unroll
        for (int i = 0; i < 2; ++i)
#pragma unroll
            for (int j = 0; j < 2; ++j) wmma::fill_fragment(acc[g][i][j], 0.f);

    for (int k0 = 0; k0 < D_IN; k0 += 32) {
#pragma unroll
        for (int r = 0; r < 2; ++r) {
            int f = tid + r * 256;
            int row = f >> 2, seg = f & 3;
            int gr = bm + row; if (gr >= N_NODES) gr = N_NODES - 1;
            *(uint4*)&sm.t.A[row * 40 + seg * 8] =
                *(const uint4*)(g_cat + (size_t)gr * D_CAT + k0 + seg * 8);
        }
        {
            int row = tid >> 3, seg = tid & 7;
#pragma unroll
            for (int g = 0; g < 2; ++g)
                *(uint4*)&sm.t.B[g][row * 72 + seg * 8] =
                    *(const uint4*)(g_Wh + (size_t)(k0 + row) * D_HID + bn0 + g * 256 + seg * 8);
        }
        __syncthreads();
#pragma unroll
        for (int kk = 0; kk < 2; ++kk) {
            wmma::fragment<wmma::matrix_a, 16, 16, 16, __half, wmma::row_major> af[2];
#pragma unroll
            for (int i = 0; i < 2; ++i)
                wmma::load_matrix_sync(af[i], &sm.t.A[(wm * 32 + i * 16) * 40 + kk * 16], 40);
#pragma unroll
            for (int g = 0; g < 2; ++g) {
                wmma::fragment<wmma::matrix_b, 16, 16, 16, __half, wmma::row_major> bf[2];
#pragma unroll
                for (int j = 0; j < 2; ++j)
                    wmma::load_matrix_sync(bf[j], &sm.t.B[g][(kk * 16) * 72 + wn * 32 + j * 16], 72);
#pragma unroll
                for (int i = 0; i < 2; ++i)
#pragma unroll
                    for (int j = 0; j < 2; ++j)
                        wmma::mma_sync(acc[g][i][j], af[i], bf[j], acc[g][i][j]);
            }
        }
        __syncthreads();
    }

    float* cw = &sm.C[warp * 32 * 36];
    int r = lane;
    int gr = bm + wm * 32 + r;
#pragma unroll
    for (int g = 0; g < 2; ++g) {
#pragma unroll
        for (int i = 0; i < 2; ++i)
#pragma unroll
            for (int j = 0; j < 2; ++j)
                wmma::store_matrix_sync(&cw[(i * 16) * 36 + j * 16], acc[g][i][j], 36, wmma::mem_row_major);
        __syncwarp();
        if (gr < N_NODES) {
            int cbase = bn0 + g * 256 + wn * 32;
            union { __half h[8]; uint4 u; } pk;
#pragma unroll
            for (int q = 0; q < 4; ++q) {
#pragma unroll
                for (int c = 0; c < 8; ++c) {
                    int col = q * 8 + c;
                    float v = cw[r * 36 + col] + bias[cbase + col];
                    pk.h[c] = __float2half_rn(fmaxf(v, 0.f));
                }
                *(uint4*)(g_Zh + (size_t)gr * D_HID + cbase + q * 8) = pk.u;
            }
        }
        __syncwarp();
    }
}

// ---------------- segment max over buckets -> fp16 into g_cat[:,128:640] ----------------
// one 128-thread block per node; thread t owns cols [4t, 4t+4)
__global__ __launch_bounds__(128) void segmax_kernel() {
    int n = blockIdx.x;
    int t = threadIdx.x;
    int deg = g_deg[n];
    if (deg > CAP) deg = CAP;
    const int* lst = g_elist + (size_t)n * CAP;

    __half2 m0 = __float2half2_rn(0.f);
    __half2 m1 = __float2half2_rn(0.f);

    int i = 0;
    for (; i + 7 < deg; i += 8) {
        int e[8];
#pragma unroll
        for (int q = 0; q < 8; ++q) e[q] = lst[i + q];
        uint2 v[8];
#pragma unroll
        for (int q = 0; q < 8; ++q)
            v[q] = *(const uint2*)(g_Zh + (size_t)e[q] * D_HID + t * 4);
#pragma unroll
        for (int q = 0; q < 8; ++q) {
            m0 = __hmax2(m0, *(const __half2*)&v[q].x);
            m1 = __hmax2(m1, *(const __half2*)&v[q].y);
        }
    }
    for (; i + 1 < deg; i += 2) {
        int e0 = lst[i];
        int e1 = lst[i + 1];
        uint2 v0 = *(const uint2*)(g_Zh + (size_t)e0 * D_HID + t * 4);
        uint2 v1 = *(const uint2*)(g_Zh + (size_t)e1 * D_HID + t * 4);
        m0 = __hmax2(m0, *(const __half2*)&v0.x);
        m1 = __hmax2(m1, *(const __half2*)&v0.y);
        m0 = __hmax2(m0, *(const __half2*)&v1.x);
        m1 = __hmax2(m1, *(const __half2*)&v1.y);
    }
    if (i < deg) {
        int e0 = lst[i];
        uint2 v0 = *(const uint2*)(g_Zh + (size_t)e0 * D_HID + t * 4);
        m0 = __hmax2(m0, *(const __half2*)&v0.x);
        m1 = __hmax2(m1, *(const __half2*)&v0.y);
    }

    uint2 o;
    *(__half2*)&o.x = m0;
    *(__half2*)&o.y = m1;
    *(uint2*)(g_cat + (size_t)n * D_CAT + D_IN + t * 4) = o;
}

// ---------------- out partial GEMM over K range, optional accumulate ----------------
template<int KBEG, int KEND, int ACC>
__global__ __launch_bounds__(256) void gemm_out_part(float* __restrict__ out) {
    __shared__ __half As[128 * 40];
    __shared__ __half Bs[32 * 136];

    const int bm = blockIdx.x * 128;
    const int tid = threadIdx.x;
    const int warp = tid >> 5;
    const int wm = warp >> 1;
    const int wn = warp & 1;

    wmma::fragment<wmma::accumulator, 16, 16, 16, float> acc[2][4];
    if (ACC) {
#pragma unroll
        for (int i = 0; i < 2; ++i) {
            int gr0 = bm + wm * 32 + i * 16;
            if (gr0 + 16 <= N_NODES) {
#pragma unroll
                for (int j = 0; j < 4; ++j)
                    wmma::load_matrix_sync(acc[i][j],
                        out + (size_t)gr0 * D_OUT + wn * 64 + j * 16, D_OUT, wmma::mem_row_major);
            }
        }
    } else {
#pragma unroll
        for (int i = 0; i < 2; ++i)
#pragma unroll
            for (int j = 0; j < 4; ++j) wmma::fill_fragment(acc[i][j], 0.f);
    }

    for (int k0 = KBEG; k0 < KEND; k0 += 32) {
#pragma unroll
        for (int r = 0; r < 2; ++r) {
            int f = tid + r * 256;
            int row = f >> 2, seg = f & 3;
            int gr = bm + row; if (gr >= N_NODES) gr = N_NODES - 1;
            *(uint4*)&As[row * 40 + seg * 8] =
                *(const uint4*)(g_cat + (size_t)gr * D_CAT + k0 + seg * 8);
        }
#pragma unroll
        for (int r = 0; r < 2; ++r) {
            int f = tid + r * 256;
            int row = f >> 4, seg = f & 15;
            *(uint4*)&Bs[row * 136 + seg * 8] =
                *(const uint4*)(g_W2h + (size_t)(k0 + row) * D_OUT + seg * 8);
        }
        __syncthreads();
#pragma unroll
        for (int kk = 0; kk < 2; ++kk) {
            wmma::fragment<wmma::matrix_a, 16, 16, 16, __half, wmma::row_major> af[2];
            wmma::fragment<wmma::matrix_b, 16, 16, 16, __half, wmma::row_major> bf[4];
#pragma unroll
            for (int i = 0; i < 2; ++i)
                wmma::load_matrix_sync(af[i], &As[(wm * 32 + i * 16) * 40 + kk * 16], 40);
#pragma unroll
            for (int j = 0; j < 4; ++j)
                wmma::load_matrix_sync(bf[j], &Bs[(kk * 16) * 136 + wn * 64 + j * 16], 136);
#pragma unroll
            for (int i = 0; i < 2; ++i)
#pragma unroll
                for (int j = 0; j < 4; ++j)
                    wmma::mma_sync(acc[i][j], af[i], bf[j], acc[i][j]);
        }
        __syncthreads();
    }

#pragma unroll
    for (int i = 0; i < 2; ++i) {
        int gr0 = bm + wm * 32 + i * 16;
        if (gr0 + 16 <= N_NODES) {
#pragma unroll
            for (int j = 0; j < 4; ++j)
                wmma::store_matrix_sync(out + (size_t)gr0 * D_OUT + wn * 64 + j * 16,
                                        acc[i][j], D_OUT, wmma::mem_row_major);
        }
    }
}

// ---------------- launch ----------------
extern "C" void kernel_launch(void* const* d_in, const int* in_sizes, int n_in,
                              void* d_out, int out_size) {
    const float* input = nullptr;
    const float* fc_w  = nullptr;
    const float* fc_b  = nullptr;
    const float* w_out = nullptr;
    const int*   adj   = nullptr;
    for (int i = 0; i < n_in; ++i) {
        switch (in_sizes[i]) {
            case 6400000: input = (const float*)d_in[i]; break;
            case 65536:   fc_w  = (const float*)d_in[i]; break;
            case 512:     fc_b  = (const float*)d_in[i]; break;
            case 81920:   w_out = (const float*)d_in[i]; break;
            case 1600000: adj   = (const int*)d_in[i]; break;
            default: break;
        }
    }
    float* out = (float*)d_out;
    (void)out_size;
    if (!input || !fc_w || !fc_b || !w_out || !adj) return;

    cudaStream_t sCSR, sX;
    cudaStreamCreateWithFlags(&sCSR, cudaStreamNonBlocking);
    cudaStreamCreateWithFlags(&sX, cudaStreamNonBlocking);
    cudaEvent_t evFork, evCSR, evConv, evOutX;
    cudaEventCreateWithFlags(&evFork, cudaEventDisableTiming);
    cudaEventCreateWithFlags(&evCSR, cudaEventDisableTiming);
    cudaEventCreateWithFlags(&evConv, cudaEventDisableTiming);
    cudaEventCreateWithFlags(&evOutX, cudaEventDisableTiming);

    cudaEventRecord(evFork, 0);
    cudaStreamWaitEvent(sCSR, evFork, 0);

    // --- side stream 1: bucketed adjacency build (2 kernels, no scan) ---
    zero_kernel<<<(N_NODES + 255) / 256, 256, 0, sCSR>>>();
    scatter_kernel<<<(N_EDGES + 255) / 256, 256, 0, sCSR>>>(adj);
    cudaEventRecord(evCSR, sCSR);

    // --- main stream: conversions + Z GEMM ---
    conv_all_kernel<<<(CONV_X_VECS + 255) / 256, 256>>>(input, fc_w, w_out);
    cudaEventRecord(evConv, 0);
    dim3 gA(4, (N_NODES + 127) / 128);
    gemm_relu_wmma<<<gA, 256>>>(fc_b);

    // --- side stream 2: out X-part (needs only conv) ---
    cudaStreamWaitEvent(sX, evConv, 0);
    gemm_out_part<0, D_IN, 0><<<(N_NODES + 127) / 128, 256, 0, sX>>>(out);
    cudaEventRecord(evOutX, sX);

    // --- segmax (needs buckets + Z) ---
    cudaStreamWaitEvent(0, evCSR, 0);
    segmax_kernel<<<N_NODES, 128>>>();

    // --- out agg-part, accumulating into out ---
    cudaStreamWaitEvent(0, evOutX, 0);
    gemm_out_part<D_IN, D_CAT, 1><<<(N_NODES + 127) / 128, 256>>>(out);

    cudaEventDestroy(evFork);
    cudaEventDestroy(evCSR);
    cudaEventDestroy(evConv);
    cudaEventDestroy(evOutX);
    cudaStreamDestroy(sCSR);
    cudaStreamDestroy(sX);
}

// round 13
// speedup vs baseline: 1.0210x; 1.0210x over previous
#include <cuda_runtime.h>
#include <cuda_fp16.h>
#include <cuda_pipeline.h>
#include <mma.h>
#include <cstdint>

using namespace nvcuda;

#define N_NODES 50000
#define N_EDGES 800000
#define D_IN    128
#define D_HID   512
#define D_OUT   128
#define D_CAT   (D_IN + D_HID)
#define CAP     128                       // slots per node (max degree ~36 for this dist)

// ---------------- device scratch (no allocations allowed) ----------------
__device__ __align__(16) __half g_Zh[(size_t)N_NODES * D_HID];   // relu(x@W+b) fp16
__device__ __align__(16) __half g_cat[(size_t)N_NODES * D_CAT];  // [Xh | agg_h]
__device__ __align__(16) __half g_Wh[(size_t)D_IN * D_HID];      // fc_w fp16
__device__ __align__(16) __half g_W2h[(size_t)D_CAT * D_OUT];    // weights fp16
__device__ __align__(16) int    g_deg[N_NODES];
__device__ __align__(16) int    g_elist[(size_t)N_NODES * CAP];  // bucketed targets

// ---------------- zero degree counters ----------------
__global__ __launch_bounds__(256) void zero_kernel() {
    int i = blockIdx.x * blockDim.x + threadIdx.x;
    if (i < N_NODES) g_deg[i] = 0;
}

// ---------------- direct bucket scatter (adjacency is int32 — proven R2/R3) ----------------
__global__ void scatter_kernel(const int* __restrict__ adj) {
    int e = blockIdx.x * blockDim.x + threadIdx.x;
    if (e < N_EDGES) {
        int src = adj[e];
        int trg = adj[N_EDGES + e];
        if ((unsigned)src < (unsigned)N_NODES && (unsigned)trg < (unsigned)N_NODES) {
            int pos = atomicAdd(&g_deg[src], 1);
            if (pos < CAP)
                g_elist[(size_t)src * CAP + pos] = trg;
        }
    }
}

// ---------------- conversions to fp16 ----------------
#define CONV_X_VECS (N_NODES * D_IN / 8)             // 800000 uint4s
__global__ void conv_all_kernel(const float* __restrict__ X,
                                const float* __restrict__ fcw,
                                const float* __restrict__ w2) {
    int idx = blockIdx.x * blockDim.x + threadIdx.x;
    if (idx < CONV_X_VECS) {
        int i = idx * 8;
        int row = i >> 7;
        int col = i & 127;
        float4 a = *(const float4*)(X + i);
        float4 b = *(const float4*)(X + i + 4);
        union { __half h[8]; uint4 u; } pk;
        pk.h[0] = __float2half_rn(a.x); pk.h[1] = __float2half_rn(a.y);
        pk.h[2] = __float2half_rn(a.z); pk.h[3] = __float2half_rn(a.w);
        pk.h[4] = __float2half_rn(b.x); pk.h[5] = __float2half_rn(b.y);
        pk.h[6] = __float2half_rn(b.z); pk.h[7] = __float2half_rn(b.w);
        *(uint4*)(g_cat + (size_t)row * D_CAT + col) = pk.u;
    }
    if (idx < D_IN * D_HID) g_Wh[idx] = __float2half_rn(fcw[idx]);
    if (idx < D_CAT * D_OUT) g_W2h[idx] = __float2half_rn(w2[idx]);
}

// ---------------- Z = relu(Xh @ Wh + b), dual column tiles, cp.async 2-stage ----------------
__global__ __launch_bounds__(256) void gemm_relu_wmma(const float* __restrict__ bias) {
    __shared__ union SMem {
        struct { __half A[2][128 * 40]; __half B[2][2][32 * 72]; } t;  // 2 stages
        float C[8 * 32 * 36];
    } sm;

    const int bm = blockIdx.y * 128;
    const int bn0 = blockIdx.x * 64;   // group 0: bn0, group 1: bn0+256
    const int tid = threadIdx.x;
    const int warp = tid >> 5;
    const int lane = tid & 31;
    const int wm = warp >> 1;
    const int wn = warp & 1;

    // per-thread tile-load coordinates
    const int a_row0 = tid >> 1;              // with r offset below
    const int b_row = tid >> 3, b_seg = tid & 7;

    auto load_stage = [&](int s, int k0) {
#pragma unroll
        for (int r = 0; r < 2; ++r) {
            int f = tid + r * 256;
            int row = f >> 2, q = f & 3;
            int gr = bm + row; if (gr >= N_NODES) gr = N_NODES - 1;
            __pipeline_memcpy_async(&sm.t.A[s][row * 40 + q * 8],
                                    g_cat + (size_t)gr * D_CAT + k0 + q * 8, 16);
        }
#pragma unroll
        for (int g = 0; g < 2; ++g)
            __pipeline_memcpy_async(&sm.t.B[s][g][b_row * 72 + b_seg * 8],
                                    g_Wh + (size_t)(k0 + b_row) * D_HID + bn0 + g * 256 + b_seg * 8, 16);
    };
    (void)a_row0;

    wmma::fragment<wmma::accumulator, 16, 16, 16, float> acc[2][2][2];
#pragma unroll
    for (int g = 0; g < 2; ++g)
#pragma unroll
        for (int i = 0; i < 2; ++i)
#pragma unroll
            for (int j = 0; j < 2; ++j) wmma::fill_fragment(acc[g][i][j], 0.f);

    load_stage(0, 0);
    __pipeline_commit();

    const int NIT = D_IN / 32;   // 4
    for (int it = 0; it < NIT; ++it) {
        if (it + 1 < NIT) {
            load_stage((it + 1) & 1, (it + 1) * 32);
            __pipeline_commit();
            __pipeline_wait_prior(1);
        } else {
            __pipeline_wait_prior(0);
        }
        __syncthreads();

        const int cur = it & 1;
#pragma unroll
        for (int kk = 0; kk < 2; ++kk) {
            wmma::fragment<wmma::matrix_a, 16, 16, 16, __half, wmma::row_major> af[2];
#pragma unroll
            for (int i = 0; i < 2; ++i)
                wmma::load_matrix_sync(af[i], &sm.t.A[cur][(wm * 32 + i * 16) * 40 + kk * 16], 40);
#pragma unroll
            for (int g = 0; g < 2; ++g) {
                wmma::fragment<wmma::matrix_b, 16, 16, 16, __half, wmma::row_major> bf[2];
#pragma unroll
                for (int j = 0; j < 2; ++j)
                    wmma::load_matrix_sync(bf[j], &sm.t.B[cur][g][(kk * 16) * 72 + wn * 32 + j * 16], 72);
#pragma unroll
                for (int i = 0; i < 2; ++i)
#pragma unroll
                    for (int j = 0; j < 2; ++j)
                        wmma::mma_sync(acc[g][i][j], af[i], bf[j], acc[g][i][j]);
            }
        }
        __syncthreads();
    }

    float* cw = &sm.C[warp * 32 * 36];
    int r = lane;
    int gr = bm + wm * 32 + r;
#pragma unroll
    for (int g = 0; g < 2; ++g) {
#pragma unroll
        for (int i = 0; i < 2; ++i)
#pragma unroll
            for (int j = 0; j < 2; ++j)
                wmma::store_matrix_sync(&cw[(i * 16) * 36 + j * 16], acc[g][i][j], 36, wmma::mem_row_major);
        __syncwarp();
        if (gr < N_NODES) {
            int cbase = bn0 + g * 256 + wn * 32;
            union { __half h[8]; uint4 u; } pk;
#pragma unroll
            for (int q = 0; q < 4; ++q) {
#pragma unroll
                for (int c = 0; c < 8; ++c) {
                    int col = q * 8 + c;
                    float v = cw[r * 36 + col] + bias[cbase + col];
                    pk.h[c] = __float2half_rn(fmaxf(v, 0.f));
                }
                *(uint4*)(g_Zh + (size_t)gr * D_HID + cbase + q * 8) = pk.u;
            }
        }
        __syncwarp();
    }
}

// ---------------- segment max over buckets -> fp16 into g_cat[:,128:640] ----------------
__global__ __launch_bounds__(128) void segmax_kernel() {
    int n = blockIdx.x;
    int t = threadIdx.x;
    int deg = g_deg[n];
    if (deg > CAP) deg = CAP;
    const int* lst = g_elist + (size_t)n * CAP;

    __half2 m0 = __float2half2_rn(0.f);
    __half2 m1 = __float2half2_rn(0.f);

    int i = 0;
    for (; i + 7 < deg; i += 8) {
        int e[8];
#pragma unroll
        for (int q = 0; q < 8; ++q) e[q] = lst[i + q];
        uint2 v[8];
#pragma unroll
        for (int q = 0; q < 8; ++q)
            v[q] = *(const uint2*)(g_Zh + (size_t)e[q] * D_HID + t * 4);
#pragma unroll
        for (int q = 0; q < 8; ++q) {
            m0 = __hmax2(m0, *(const __half2*)&v[q].x);
            m1 = __hmax2(m1, *(const __half2*)&v[q].y);
        }
    }
    for (; i + 1 < deg; i += 2) {
        int e0 = lst[i];
        int e1 = lst[i + 1];
        uint2 v0 = *(const uint2*)(g_Zh + (size_t)e0 * D_HID + t * 4);
        uint2 v1 = *(const uint2*)(g_Zh + (size_t)e1 * D_HID + t * 4);
        m0 = __hmax2(m0, *(const __half2*)&v0.x);
        m1 = __hmax2(m1, *(const __half2*)&v0.y);
        m0 = __hmax2(m0, *(const __half2*)&v1.x);
        m1 = __hmax2(m1, *(const __half2*)&v1.y);
    }
    if (i < deg) {
        int e0 = lst[i];
        uint2 v0 = *(const uint2*)(g_Zh + (size_t)e0 * D_HID + t * 4);
        m0 = __hmax2(m0, *(const __half2*)&v0.x);
        m1 = __hmax2(m1, *(const __half2*)&v0.y);
    }

    uint2 o;
    *(__half2*)&o.x = m0;
    *(__half2*)&o.y = m1;
    *(uint2*)(g_cat + (size_t)n * D_CAT + D_IN + t * 4) = o;
}

// ---------------- out partial GEMM over K range, optional accumulate ----------------
template<int KBEG, int KEND, int ACC>
__global__ __launch_bounds__(256) void gemm_out_part(float* __restrict__ out) {
    __shared__ __half As[128 * 40];
    __shared__ __half Bs[32 * 136];

    const int bm = blockIdx.x * 128;
    const int tid = threadIdx.x;
    const int warp = tid >> 5;
    const int wm = warp >> 1;
    const int wn = warp & 1;

    wmma::fragment<wmma::accumulator, 16, 16, 16, float> acc[2][4];
    if (ACC) {
#pragma unroll
        for (int i = 0; i < 2; ++i) {
            int gr0 = bm + wm * 32 + i * 16;
            if (gr0 + 16 <= N_NODES) {
#pragma unroll
                for (int j = 0; j < 4; ++j)
                    wmma::load_matrix_sync(acc[i][j],
                        out + (size_t)gr0 * D_OUT + wn * 64 + j * 16, D_OUT, wmma::mem_row_major);
            }
        }
    } else {
#pragma unroll
        for (int i = 0; i < 2; ++i)
#pragma unroll
            for (int j = 0; j < 4; ++j) wmma::fill_fragment(acc[i][j], 0.f);
    }

    for (int k0 = KBEG; k0 < KEND; k0 += 32) {
#pragma unroll
        for (int r = 0; r < 2; ++r) {
            int f = tid + r * 256;
            int row = f >> 2, seg = f & 3;
            int gr = bm + row; if (gr >= N_NODES) gr = N_NODES - 1;
            *(uint4*)&As[row * 40 + seg * 8] =
                *(const uint4*)(g_cat + (size_t)gr * D_CAT + k0 + seg * 8);
        }
#pragma unroll
        for (int r = 0; r < 2; ++r) {
            int f = tid + r * 256;
            int row = f >> 4, seg = f & 15;
            *(uint4*)&Bs[row * 136 + seg * 8] =
                *(const uint4*)(g_W2h + (size_t)(k0 + row) * D_OUT + seg * 8);
        }
        __syncthreads();
#pragma unroll
        for (int kk = 0; kk < 2; ++kk) {
            wmma::fragment<wmma::matrix_a, 16, 16, 16, __half, wmma::row_major> af[2];
            wmma::fragment<wmma::matrix_b, 16, 16, 16, __half, wmma::row_major> bf[4];
#pragma unroll
            for (int i = 0; i < 2; ++i)
                wmma::load_matrix_sync(af[i], &As[(wm * 32 + i * 16) * 40 + kk * 16], 40);
#pragma unroll
            for (int j = 0; j < 4; ++j)
                wmma::load_matrix_sync(bf[j], &Bs[(kk * 16) * 136 + wn * 64 + j * 16], 136);
#pragma unroll
            for (int i = 0; i < 2; ++i)
#pragma unroll
                for (int j = 0; j < 4; ++j)
                    wmma::mma_sync(acc[i][j], af[i], bf[j], acc[i][j]);
        }
        __syncthreads();
    }

#pragma unroll
    for (int i = 0; i < 2; ++i) {
        int gr0 = bm + wm * 32 + i * 16;
        if (gr0 + 16 <= N_NODES) {
#pragma unroll
            for (int j = 0; j < 4; ++j)
                wmma::store_matrix_sync(out + (size_t)gr0 * D_OUT + wn * 64 + j * 16,
                                        acc[i][j], D_OUT, wmma::mem_row_major);
        }
    }
}

// ---------------- launch ----------------
extern "C" void kernel_launch(void* const* d_in, const int* in_sizes, int n_in,
                              void* d_out, int out_size) {
    const float* input = nullptr;
    const float* fc_w  = nullptr;
    const float* fc_b  = nullptr;
    const float* w_out = nullptr;
    const int*   adj   = nullptr;
    for (int i = 0; i < n_in; ++i) {
        switch (in_sizes[i]) {
            case 6400000: input = (const float*)d_in[i]; break;
            case 65536:   fc_w  = (const float*)d_in[i]; break;
            case 512:     fc_b  = (const float*)d_in[i]; break;
            case 81920:   w_out = (const float*)d_in[i]; break;
            case 1600000: adj   = (const int*)d_in[i]; break;
            default: break;
        }
    }
    float* out = (float*)d_out;
    (void)out_size;
    if (!input || !fc_w || !fc_b || !w_out || !adj) return;

    cudaStream_t sCSR, sX;
    cudaStreamCreateWithFlags(&sCSR, cudaStreamNonBlocking);
    cudaStreamCreateWithFlags(&sX, cudaStreamNonBlocking);
    cudaEvent_t evFork, evCSR, evConv, evOutX;
    cudaEventCreateWithFlags(&evFork, cudaEventDisableTiming);
    cudaEventCreateWithFlags(&evCSR, cudaEventDisableTiming);
    cudaEventCreateWithFlags(&evConv, cudaEventDisableTiming);
    cudaEventCreateWithFlags(&evOutX, cudaEventDisableTiming);

    cudaEventRecord(evFork, 0);
    cudaStreamWaitEvent(sCSR, evFork, 0);

    // --- side stream 1: bucketed adjacency build ---
    zero_kernel<<<(N_NODES + 255) / 256, 256, 0, sCSR>>>();
    scatter_kernel<<<(N_EDGES + 255) / 256, 256, 0, sCSR>>>(adj);
    cudaEventRecord(evCSR, sCSR);

    // --- main stream: conversions + Z GEMM (cp.async pipelined) ---
    conv_all_kernel<<<(CONV_X_VECS + 255) / 256, 256>>>(input, fc_w, w_out);
    cudaEventRecord(evConv, 0);
    dim3 gA(4, (N_NODES + 127) / 128);
    gemm_relu_wmma<<<gA, 256>>>(fc_b);

    // --- side stream 2: out X-part (needs only conv) ---
    cudaStreamWaitEvent(sX, evConv, 0);
    gemm_out_part<0, D_IN, 0><<<(N_NODES + 127) / 128, 256, 0, sX>>>(out);
    cudaEventRecord(evOutX, sX);

    // --- segmax (needs buckets + Z) ---
    cudaStreamWaitEvent(0, evCSR, 0);
    segmax_kernel<<<N_NODES, 128>>>();

    // --- out agg-part, accumulating into out ---
    cudaStreamWaitEvent(0, evOutX, 0);
    gemm_out_part<D_IN, D_CAT, 1><<<(N_NODES + 127) / 128, 256>>>(out);

    cudaEventDestroy(evFork);
    cudaEventDestroy(evCSR);
    cudaEventDestroy(evConv);
    cudaEventDestroy(evOutX);
    cudaStreamDestroy(sCSR);
    cudaStreamDestroy(sX);
}

// round 14
// speedup vs baseline: 1.0554x; 1.0337x over previous
#include <cuda_runtime.h>
#include <cuda_fp16.h>
#include <cuda_pipeline.h>
#include <mma.h>
#include <cstdint>

using namespace nvcuda;

#define N_NODES 50000
#define N_EDGES 800000
#define D_IN    128
#define D_HID   512
#define D_OUT   128
#define D_CAT   (D_IN + D_HID)
#define CAP     128                       // slots per node (max degree ~36 for this dist)

// ---------------- device scratch (no allocations allowed) ----------------
__device__ __align__(16) __half g_Zh[(size_t)N_NODES * D_HID];   // relu(x@W+b) fp16
__device__ __align__(16) __half g_cat[(size_t)N_NODES * D_CAT];  // [Xh | agg_h]
__device__ __align__(16) __half g_Wh[(size_t)D_IN * D_HID];      // fc_w fp16
__device__ __align__(16) __half g_W2h[(size_t)D_CAT * D_OUT];    // weights fp16
__device__ __align__(16) int    g_deg[N_NODES];
__device__ __align__(16) int    g_elist[(size_t)N_NODES * CAP];  // bucketed targets

// ---------------- zero degree counters ----------------
__global__ __launch_bounds__(256) void zero_kernel() {
    int i = blockIdx.x * blockDim.x + threadIdx.x;
    if (i < N_NODES) g_deg[i] = 0;
}

// ---------------- direct bucket scatter (adjacency is int32 — proven R2/R3) ----------------
__global__ void scatter_kernel(const int* __restrict__ adj) {
    int e = blockIdx.x * blockDim.x + threadIdx.x;
    if (e < N_EDGES) {
        int src = adj[e];
        int trg = adj[N_EDGES + e];
        if ((unsigned)src < (unsigned)N_NODES && (unsigned)trg < (unsigned)N_NODES) {
            int pos = atomicAdd(&g_deg[src], 1);
            if (pos < CAP)
                g_elist[(size_t)src * CAP + pos] = trg;
        }
    }
}

// ---------------- conversions to fp16 ----------------
#define CONV_X_VECS (N_NODES * D_IN / 8)             // 800000 uint4s
__global__ void conv_all_kernel(const float* __restrict__ X,
                                const float* __restrict__ fcw,
                                const float* __restrict__ w2) {
    int idx = blockIdx.x * blockDim.x + threadIdx.x;
    if (idx < CONV_X_VECS) {
        int i = idx * 8;
        int row = i >> 7;
        int col = i & 127;
        float4 a = *(const float4*)(X + i);
        float4 b = *(const float4*)(X + i + 4);
        union { __half h[8]; uint4 u; } pk;
        pk.h[0] = __float2half_rn(a.x); pk.h[1] = __float2half_rn(a.y);
        pk.h[2] = __float2half_rn(a.z); pk.h[3] = __float2half_rn(a.w);
        pk.h[4] = __float2half_rn(b.x); pk.h[5] = __float2half_rn(b.y);
        pk.h[6] = __float2half_rn(b.z); pk.h[7] = __float2half_rn(b.w);
        *(uint4*)(g_cat + (size_t)row * D_CAT + col) = pk.u;
    }
    if (idx < D_IN * D_HID) g_Wh[idx] = __float2half_rn(fcw[idx]);
    if (idx < D_CAT * D_OUT) g_W2h[idx] = __float2half_rn(w2[idx]);
}

// ---------------- Z = relu(Xh @ Wh + b), single 64-col tile, cp.async 2-stage ----------------
// BM=128, BN=64, BK=32, 8 warps 4(M)x2(N), warp tile 32x32. 3 CTAs/SM target.
__global__ __launch_bounds__(256, 3) void gemm_relu_wmma(const float* __restrict__ bias) {
    __shared__ union SMem {
        struct { __half A[2][128 * 40]; __half B[2][32 * 72]; } t;  // 2 stages
        float C[8 * 32 * 36];
    } sm;

    const int bm = blockIdx.y * 128;
    const int bn = blockIdx.x * 64;
    const int tid = threadIdx.x;
    const int warp = tid >> 5;
    const int lane = tid & 31;
    const int wm = warp >> 1;
    const int wn = warp & 1;

    const int b_row = tid >> 3, b_seg = tid & 7;

    auto load_stage = [&](int s, int k0) {
#pragma unroll
        for (int r = 0; r < 2; ++r) {
            int f = tid + r * 256;
            int row = f >> 2, q = f & 3;
            int gr = bm + row; if (gr >= N_NODES) gr = N_NODES - 1;
            __pipeline_memcpy_async(&sm.t.A[s][row * 40 + q * 8],
                                    g_cat + (size_t)gr * D_CAT + k0 + q * 8, 16);
        }
        __pipeline_memcpy_async(&sm.t.B[s][b_row * 72 + b_seg * 8],
                                g_Wh + (size_t)(k0 + b_row) * D_HID + bn + b_seg * 8, 16);
    };

    wmma::fragment<wmma::accumulator, 16, 16, 16, float> acc[2][2];
#pragma unroll
    for (int i = 0; i < 2; ++i)
#pragma unroll
        for (int j = 0; j < 2; ++j) wmma::fill_fragment(acc[i][j], 0.f);

    load_stage(0, 0);
    __pipeline_commit();

    const int NIT = D_IN / 32;   // 4
    for (int it = 0; it < NIT; ++it) {
        if (it + 1 < NIT) {
            load_stage((it + 1) & 1, (it + 1) * 32);
            __pipeline_commit();
            __pipeline_wait_prior(1);
        } else {
            __pipeline_wait_prior(0);
        }
        __syncthreads();

        const int cur = it & 1;
#pragma unroll
        for (int kk = 0; kk < 2; ++kk) {
            wmma::fragment<wmma::matrix_a, 16, 16, 16, __half, wmma::row_major> af[2];
            wmma::fragment<wmma::matrix_b, 16, 16, 16, __half, wmma::row_major> bf[2];
#pragma unroll
            for (int i = 0; i < 2; ++i)
                wmma::load_matrix_sync(af[i], &sm.t.A[cur][(wm * 32 + i * 16) * 40 + kk * 16], 40);
#pragma unroll
            for (int j = 0; j < 2; ++j)
                wmma::load_matrix_sync(bf[j], &sm.t.B[cur][(kk * 16) * 72 + wn * 32 + j * 16], 72);
#pragma unroll
            for (int i = 0; i < 2; ++i)
#pragma unroll
                for (int j = 0; j < 2; ++j)
                    wmma::mma_sync(acc[i][j], af[i], bf[j], acc[i][j]);
        }
        __syncthreads();
    }

    float* cw = &sm.C[warp * 32 * 36];
#pragma unroll
    for (int i = 0; i < 2; ++i)
#pragma unroll
        for (int j = 0; j < 2; ++j)
            wmma::store_matrix_sync(&cw[(i * 16) * 36 + j * 16], acc[i][j], 36, wmma::mem_row_major);
    __syncwarp();

    int r = lane;
    int gr = bm + wm * 32 + r;
    if (gr < N_NODES) {
        int cbase = bn + wn * 32;
        union { __half h[8]; uint4 u; } pk;
#pragma unroll
        for (int q = 0; q < 4; ++q) {
#pragma unroll
            for (int c = 0; c < 8; ++c) {
                int col = q * 8 + c;
                float v = cw[r * 36 + col] + bias[cbase + col];
                pk.h[c] = __float2half_rn(fmaxf(v, 0.f));
            }
            *(uint4*)(g_Zh + (size_t)gr * D_HID + cbase + q * 8) = pk.u;
        }
    }
}

// ---------------- segment max over buckets -> fp16 into g_cat[:,128:640] ----------------
__global__ __launch_bounds__(128) void segmax_kernel() {
    int n = blockIdx.x;
    int t = threadIdx.x;
    int deg = g_deg[n];
    if (deg > CAP) deg = CAP;
    const int* lst = g_elist + (size_t)n * CAP;

    __half2 m0 = __float2half2_rn(0.f);
    __half2 m1 = __float2half2_rn(0.f);

    int i = 0;
    for (; i + 7 < deg; i += 8) {
        int e[8];
#pragma unroll
        for (int q = 0; q < 8; ++q) e[q] = lst[i + q];
        uint2 v[8];
#pragma unroll
        for (int q = 0; q < 8; ++q)
            v[q] = *(const uint2*)(g_Zh + (size_t)e[q] * D_HID + t * 4);
#pragma unroll
        for (int q = 0; q < 8; ++q) {
            m0 = __hmax2(m0, *(const __half2*)&v[q].x);
            m1 = __hmax2(m1, *(const __half2*)&v[q].y);
        }
    }
    for (; i + 1 < deg; i += 2) {
        int e0 = lst[i];
        int e1 = lst[i + 1];
        uint2 v0 = *(const uint2*)(g_Zh + (size_t)e0 * D_HID + t * 4);
        uint2 v1 = *(const uint2*)(g_Zh + (size_t)e1 * D_HID + t * 4);
        m0 = __hmax2(m0, *(const __half2*)&v0.x);
        m1 = __hmax2(m1, *(const __half2*)&v0.y);
        m0 = __hmax2(m0, *(const __half2*)&v1.x);
        m1 = __hmax2(m1, *(const __half2*)&v1.y);
    }
    if (i < deg) {
        int e0 = lst[i];
        uint2 v0 = *(const uint2*)(g_Zh + (size_t)e0 * D_HID + t * 4);
        m0 = __hmax2(m0, *(const __half2*)&v0.x);
        m1 = __hmax2(m1, *(const __half2*)&v0.y);
    }

    uint2 o;
    *(__half2*)&o.x = m0;
    *(__half2*)&o.y = m1;
    *(uint2*)(g_cat + (size_t)n * D_CAT + D_IN + t * 4) = o;
}

// ---------------- out partial GEMM over K range, cp.async 2-stage, optional accumulate ----------------
template<int KBEG, int KEND, int ACC>
__global__ __launch_bounds__(256) void gemm_out_part(float* __restrict__ out) {
    __shared__ __half As[2][128 * 40];
    __shared__ __half Bs[2][32 * 136];

    const int bm = blockIdx.x * 128;
    const int tid = threadIdx.x;
    const int warp = tid >> 5;
    const int wm = warp >> 1;
    const int wn = warp & 1;

    auto load_stage = [&](int s, int k0) {
#pragma unroll
        for (int r = 0; r < 2; ++r) {
            int f = tid + r * 256;
            int row = f >> 2, seg = f & 3;
            int gr = bm + row; if (gr >= N_NODES) gr = N_NODES - 1;
            __pipeline_memcpy_async(&As[s][row * 40 + seg * 8],
                                    g_cat + (size_t)gr * D_CAT + k0 + seg * 8, 16);
        }
#pragma unroll
        for (int r = 0; r < 2; ++r) {
            int f = tid + r * 256;
            int row = f >> 4, seg = f & 15;
            __pipeline_memcpy_async(&Bs[s][row * 136 + seg * 8],
                                    g_W2h + (size_t)(k0 + row) * D_OUT + seg * 8, 16);
        }
    };

    wmma::fragment<wmma::accumulator, 16, 16, 16, float> acc[2][4];
    if (ACC) {
#pragma unroll
        for (int i = 0; i < 2; ++i) {
            int gr0 = bm + wm * 32 + i * 16;
            if (gr0 + 16 <= N_NODES) {
#pragma unroll
                for (int j = 0; j < 4; ++j)
                    wmma::load_matrix_sync(acc[i][j],
                        out + (size_t)gr0 * D_OUT + wn * 64 + j * 16, D_OUT, wmma::mem_row_major);
            }
        }
    } else {
#pragma unroll
        for (int i = 0; i < 2; ++i)
#pragma unroll
            for (int j = 0; j < 4; ++j) wmma::fill_fragment(acc[i][j], 0.f);
    }

    load_stage(0, KBEG);
    __pipeline_commit();

    const int NIT = (KEND - KBEG) / 32;
    for (int it = 0; it < NIT; ++it) {
        if (it + 1 < NIT) {
            load_stage((it + 1) & 1, KBEG + (it + 1) * 32);
            __pipeline_commit();
            __pipeline_wait_prior(1);
        } else {
            __pipeline_wait_prior(0);
        }
        __syncthreads();

        const int cur = it & 1;
#pragma unroll
        for (int kk = 0; kk < 2; ++kk) {
            wmma::fragment<wmma::matrix_a, 16, 16, 16, __half, wmma::row_major> af[2];
            wmma::fragment<wmma::matrix_b, 16, 16, 16, __half, wmma::row_major> bf[4];
#pragma unroll
            for (int i = 0; i < 2; ++i)
                wmma::load_matrix_sync(af[i], &As[cur][(wm * 32 + i * 16) * 40 + kk * 16], 40);
#pragma unroll
            for (int j = 0; j < 4; ++j)
                wmma::load_matrix_sync(bf[j], &Bs[cur][(kk * 16) * 136 + wn * 64 + j * 16], 136);
#pragma unroll
            for (int i = 0; i < 2; ++i)
#pragma unroll
                for (int j = 0; j < 4; ++j)
                    wmma::mma_sync(acc[i][j], af[i], bf[j], acc[i][j]);
        }
        __syncthreads();
    }

#pragma unroll
    for (int i = 0; i < 2; ++i) {
        int gr0 = bm + wm * 32 + i * 16;
        if (gr0 + 16 <= N_NODES) {
#pragma unroll
            for (int j = 0; j < 4; ++j)
                wmma::store_matrix_sync(out + (size_t)gr0 * D_OUT + wn * 64 + j * 16,
                                        acc[i][j], D_OUT, wmma::mem_row_major);
        }
    }
}

// ---------------- launch ----------------
extern "C" void kernel_launch(void* const* d_in, const int* in_sizes, int n_in,
                              void* d_out, int out_size) {
    const float* input = nullptr;
    const float* fc_w  = nullptr;
    const float* fc_b  = nullptr;
    const float* w_out = nullptr;
    const int*   adj   = nullptr;
    for (int i = 0; i < n_in; ++i) {
        switch (in_sizes[i]) {
            case 6400000: input = (const float*)d_in[i]; break;
            case 65536:   fc_w  = (const float*)d_in[i]; break;
            case 512:     fc_b  = (const float*)d_in[i]; break;
            case 81920:   w_out = (const float*)d_in[i]; break;
            case 1600000: adj   = (const int*)d_in[i]; break;
            default: break;
        }
    }
    float* out = (float*)d_out;
    (void)out_size;
    if (!input || !fc_w || !fc_b || !w_out || !adj) return;

    cudaStream_t sCSR, sX;
    cudaStreamCreateWithFlags(&sCSR, cudaStreamNonBlocking);
    cudaStreamCreateWithFlags(&sX, cudaStreamNonBlocking);
    cudaEvent_t evFork, evCSR, evConv, evOutX;
    cudaEventCreateWithFlags(&evFork, cudaEventDisableTiming);
    cudaEventCreateWithFlags(&evCSR, cudaEventDisableTiming);
    cudaEventCreateWithFlags(&evConv, cudaEventDisableTiming);
    cudaEventCreateWithFlags(&evOutX, cudaEventDisableTiming);

    cudaEventRecord(evFork, 0);
    cudaStreamWaitEvent(sCSR, evFork, 0);

    // --- side stream 1: bucketed adjacency build ---
    zero_kernel<<<(N_NODES + 255) / 256, 256, 0, sCSR>>>();
    scatter_kernel<<<(N_EDGES + 255) / 256, 256, 0, sCSR>>>(adj);
    cudaEventRecord(evCSR, sCSR);

    // --- main stream: conversions + Z GEMM ---
    conv_all_kernel<<<(CONV_X_VECS + 255) / 256, 256>>>(input, fc_w, w_out);
    cudaEventRecord(evConv, 0);
    dim3 gA(D_HID / 64, (N_NODES + 127) / 128);
    gemm_relu_wmma<<<gA, 256>>>(fc_b);

    // --- side stream 2: out X-part (needs only conv) ---
    cudaStreamWaitEvent(sX, evConv, 0);
    gemm_out_part<0, D_IN, 0><<<(N_NODES + 127) / 128, 256, 0, sX>>>(out);
    cudaEventRecord(evOutX, sX);

    // --- segmax (needs buckets + Z) ---
    cudaStreamWaitEvent(0, evCSR, 0);
    segmax_kernel<<<N_NODES, 128>>>();

    // --- out agg-part, accumulating into out ---
    cudaStreamWaitEvent(0, evOutX, 0);
    gemm_out_part<D_IN, D_CAT, 1><<<(N_NODES + 127) / 128, 256>>>(out);

    cudaEventDestroy(evFork);
    cudaEventDestroy(evCSR);
    cudaEventDestroy(evConv);
    cudaEventDestroy(evOutX);
    cudaStreamDestroy(sCSR);
    cudaStreamDestroy(sX);
}